// round 3
// baseline (speedup 1.0000x reference)
#include <cuda_runtime.h>

// PlasticLinearRec: B=128, F=512
//   M[b,j,k]   = weight[j,k] + plastic_scale[j,k] * hebb[b,j,k]
//   pre[b,j]   = sum_k last_out[b,k] * M[b,j,k]
//   out[b,j]   = tanh(pre[b,j] + input[b,j])
//   hebb'[b,j,k] = hebb[b,j,k] + lr * out[b,j] * (last_out[b,k] - out[b,j]*hebb[b,j,k])
//
// Strategy: one warp per (b,j) row. Row (512 fp32) lives in registers
// (16 floats/thread, 4x float4). hebb is read from HBM exactly once and
// written exactly once — the kernel is bound by the compulsory 268 MB
// of hebb traffic. weight / plastic_scale / last_out hit L2 after the
// first wave (3 MB total working set vs 126 MB L2).

#define B_DIM 128
#define F_DIM 512
#define ROWS (B_DIM * F_DIM)   // 65536 warps total
#define THREADS 256            // 8 warps / block -> 8192 blocks

__global__ __launch_bounds__(THREADS)
void plastic_linear_rec_kernel(
    const float* __restrict__ inp,        // (B, F)
    const float* __restrict__ last_out,   // (B, F)
    const float* __restrict__ hebb,       // (B, F, F)
    const float* __restrict__ weight,     // (F, F)
    const float* __restrict__ pscale,     // (F, F)
    const float* __restrict__ plr,        // (1,)
    float* __restrict__ out,              // (B, F)
    float* __restrict__ hebb_new)         // (B, F, F)
{
    const int gwarp = (blockIdx.x * THREADS + threadIdx.x) >> 5;  // row id = b*F + j
    const int lane  = threadIdx.x & 31;
    if (gwarp >= ROWS) return;

    const int b = gwarp >> 9;          // / F
    const int j = gwarp & (F_DIM - 1); // % F

    const float4* __restrict__ h4 = (const float4*)(hebb     + (size_t)gwarp * F_DIM);
    const float4* __restrict__ w4 = (const float4*)(weight   + (size_t)j     * F_DIM);
    const float4* __restrict__ p4 = (const float4*)(pscale   + (size_t)j     * F_DIM);
    const float4* __restrict__ l4 = (const float4*)(last_out + (size_t)b     * F_DIM);

    // 512 floats / row = 128 float4 = 4 chunks of 32 lanes. Front-batch the
    // hebb loads first (the only HBM-miss stream) for maximum MLP.
    float4 h[4], l[4], w[4], p[4];
#pragma unroll
    for (int c = 0; c < 4; c++) h[c] = h4[c * 32 + lane];
#pragma unroll
    for (int c = 0; c < 4; c++) l[c] = l4[c * 32 + lane];
#pragma unroll
    for (int c = 0; c < 4; c++) w[c] = w4[c * 32 + lane];
#pragma unroll
    for (int c = 0; c < 4; c++) p[c] = p4[c * 32 + lane];

    // partial dot: last_out[k] * (weight[j,k] + pscale[j,k]*hebb[b,j,k])
    float partial = 0.0f;
#pragma unroll
    for (int c = 0; c < 4; c++) {
        partial = fmaf(l[c].x, fmaf(p[c].x, h[c].x, w[c].x), partial);
        partial = fmaf(l[c].y, fmaf(p[c].y, h[c].y, w[c].y), partial);
        partial = fmaf(l[c].z, fmaf(p[c].z, h[c].z, w[c].z), partial);
        partial = fmaf(l[c].w, fmaf(p[c].w, h[c].w, w[c].w), partial);
    }

    // warp butterfly reduce -> every lane holds the full sum
#pragma unroll
    for (int off = 16; off; off >>= 1)
        partial += __shfl_xor_sync(0xffffffffu, partial, off);

    const float o_val = tanhf(partial + __ldg(inp + gwarp));
    if (lane == 0) out[gwarp] = o_val;

    const float lro = __ldg(plr) * o_val;

    // hebb' = h + lr*o*(l - o*h)
    float4* __restrict__ hn4 = (float4*)(hebb_new + (size_t)gwarp * F_DIM);
#pragma unroll
    for (int c = 0; c < 4; c++) {
        float4 r;
        r.x = fmaf(lro, fmaf(-o_val, h[c].x, l[c].x), h[c].x);
        r.y = fmaf(lro, fmaf(-o_val, h[c].y, l[c].y), h[c].y);
        r.z = fmaf(lro, fmaf(-o_val, h[c].z, l[c].z), h[c].z);
        r.w = fmaf(lro, fmaf(-o_val, h[c].w, l[c].w), h[c].w);
        hn4[c * 32 + lane] = r;
    }
}

extern "C" void kernel_launch(void* const* d_in, const int* in_sizes, int n_in,
                              void* d_out, int out_size) {
    const float* inp   = (const float*)d_in[0];  // input        (B,F)
    const float* lo    = (const float*)d_in[1];  // last_out     (B,F)
    const float* hebb  = (const float*)d_in[2];  // hebb         (B,F,F)
    const float* w     = (const float*)d_in[3];  // weight       (F,F)
    const float* ps    = (const float*)d_in[4];  // plastic_scale(F,F)
    const float* lr    = (const float*)d_in[5];  // plastic_lr   (1,)

    float* out_p  = (float*)d_out;                // first B*F elements
    float* hebb_p = (float*)d_out + ROWS;         // remaining B*F*F elements

    const int warps_per_block = THREADS / 32;
    const int blocks = ROWS / warps_per_block;    // 8192

    plastic_linear_rec_kernel<<<blocks, THREADS>>>(inp, lo, hebb, w, ps, lr,
                                                   out_p, hebb_p);
}

// round 5
// speedup vs baseline: 1.0681x; 1.0681x over previous
#include <cuda_runtime.h>

// PlasticLinearRec: B=128, F=512
//   M[b,j,k]   = weight[j,k] + plastic_scale[j,k] * hebb[b,j,k]
//   pre[b,j]   = sum_k last_out[b,k] * M[b,j,k]
//   out[b,j]   = tanh(pre[b,j] + input[b,j])
//   hebb'[b,j,k] = hebb[b,j,k] + lr*out[b,j]*(last_out[b,k] - out[b,j]*hebb[b,j,k])
//
// One warp per (b,j) row; hebb row (512 fp32 = 16 floats/thread) read via
// __ldcs ONCE into registers, updated, written via __stcs ONCE. Kernel is
// bound by the compulsory 268 MB of hebb HBM traffic.
//
// R3: register diet (only h[] stays resident; l/w/p stream through temps,
// l re-loaded from L1 for the update) + launch_bounds(256,5) for 40 warps/SM
// + evict-first hints on the hebb streams to keep W/PS/last_out L2-resident.

#define B_DIM 128
#define F_DIM 512
#define ROWS (B_DIM * F_DIM)   // 65536 warps
#define THREADS 256            // 8 warps/block -> 8192 blocks

__global__ __launch_bounds__(THREADS, 5)
void plastic_linear_rec_kernel(
    const float* __restrict__ inp,        // (B, F)
    const float* __restrict__ last_out,   // (B, F)
    const float* __restrict__ hebb,       // (B, F, F)
    const float* __restrict__ weight,     // (F, F)
    const float* __restrict__ pscale,     // (F, F)
    const float* __restrict__ plr,        // (1,)
    float* __restrict__ out,              // (B, F)
    float* __restrict__ hebb_new)         // (B, F, F)
{
    const int gwarp = (blockIdx.x * THREADS + threadIdx.x) >> 5;  // b*F + j
    const int lane  = threadIdx.x & 31;

    const int b = gwarp >> 9;          // / F
    const int j = gwarp & (F_DIM - 1); // % F

    const float4* __restrict__ h4 = (const float4*)(hebb     + (size_t)gwarp * F_DIM);
    const float4* __restrict__ w4 = (const float4*)(weight   + (size_t)j     * F_DIM);
    const float4* __restrict__ p4 = (const float4*)(pscale   + (size_t)j     * F_DIM);
    const float4* __restrict__ l4 = (const float4*)(last_out + (size_t)b     * F_DIM);

    // hebb row: the only HBM-miss stream. Front-batch all 4 LDG.128.E.CS —
    // evict-first so it doesn't thrash W/PS/last_out out of L2.
    float4 h[4];
#pragma unroll
    for (int c = 0; c < 4; c++) h[c] = __ldcs(h4 + c * 32 + lane);

    // Dot product: l/w/p stream through per-chunk temps (L2-resident after
    // wave 1), freeing 48 bytes/thread of registers vs keeping them live.
    float acc0 = 0.0f, acc1 = 0.0f;
#pragma unroll
    for (int c = 0; c < 4; c++) {
        const float4 l = __ldg(l4 + c * 32 + lane);
        const float4 w = __ldg(w4 + c * 32 + lane);
        const float4 p = __ldg(p4 + c * 32 + lane);
        acc0 = fmaf(l.x, fmaf(p.x, h[c].x, w.x), acc0);
        acc1 = fmaf(l.y, fmaf(p.y, h[c].y, w.y), acc1);
        acc0 = fmaf(l.z, fmaf(p.z, h[c].z, w.z), acc0);
        acc1 = fmaf(l.w, fmaf(p.w, h[c].w, w.w), acc1);
    }
    float partial = acc0 + acc1;

    // butterfly reduce -> all lanes hold the sum
#pragma unroll
    for (int off = 16; off; off >>= 1)
        partial += __shfl_xor_sync(0xffffffffu, partial, off);

    const float o_val = tanhf(partial + __ldg(inp + gwarp));
    if (lane == 0) out[gwarp] = o_val;

    const float lro = __ldg(plr) * o_val;

    // hebb' = h + lr*o*(l - o*h); l re-loaded (L1 hit), written evict-first.
    float4* __restrict__ hn4 = (float4*)(hebb_new + (size_t)gwarp * F_DIM);
#pragma unroll
    for (int c = 0; c < 4; c++) {
        const float4 l = __ldg(l4 + c * 32 + lane);
        float4 r;
        r.x = fmaf(lro, fmaf(-o_val, h[c].x, l.x), h[c].x);
        r.y = fmaf(lro, fmaf(-o_val, h[c].y, l.y), h[c].y);
        r.z = fmaf(lro, fmaf(-o_val, h[c].z, l.z), h[c].z);
        r.w = fmaf(lro, fmaf(-o_val, h[c].w, l.w), h[c].w);
        __stcs(hn4 + c * 32 + lane, r);
    }
}

extern "C" void kernel_launch(void* const* d_in, const int* in_sizes, int n_in,
                              void* d_out, int out_size) {
    const float* inp   = (const float*)d_in[0];  // input         (B,F)
    const float* lo    = (const float*)d_in[1];  // last_out      (B,F)
    const float* hebb  = (const float*)d_in[2];  // hebb          (B,F,F)
    const float* w     = (const float*)d_in[3];  // weight        (F,F)
    const float* ps    = (const float*)d_in[4];  // plastic_scale (F,F)
    const float* lr    = (const float*)d_in[5];  // plastic_lr    (1,)

    float* out_p  = (float*)d_out;            // first B*F elements
    float* hebb_p = (float*)d_out + ROWS;     // remaining B*F*F elements

    const int blocks = ROWS / (THREADS / 32); // 8192
    plastic_linear_rec_kernel<<<blocks, THREADS>>>(inp, lo, hebb, w, ps, lr,
                                                   out_p, hebb_p);
}